// round 1
// baseline (speedup 1.0000x reference)
#include <cuda_runtime.h>

#define HH 512
#define WW 512
#define HWSZ (HH*WW)

// Intermediate activation buffers (static device globals — no allocation).
// Ping-pong: L0 out 64ch -> buf0, L1 out 256 -> buf1, L2 out 512 -> buf0,
// L3 out 256 -> buf1, L4 out 64 -> buf0, L5 out 1 -> buf1.
__device__ float g_buf0[512 * HWSZ];
__device__ float g_buf1[256 * HWSZ];

// ---------------------------------------------------------------------------
// Layer 0: 1->64, k=1 conv + bias + PReLU. Pure elementwise.
// ---------------------------------------------------------------------------
__global__ void layer0_kernel(const float* __restrict__ A,
                              const float* __restrict__ w,
                              const float* __restrict__ b,
                              const float* __restrict__ p) {
    int idx = blockIdx.x * blockDim.x + threadIdx.x;
    if (idx >= HWSZ) return;
    float a = A[idx];
    float alpha = p[0];
#pragma unroll
    for (int c = 0; c < 64; c++) {
        float v = fmaf(w[c], a, b[c]);
        g_buf0[c * HWSZ + idx] = v >= 0.f ? v : alpha * v;
    }
}

// ---------------------------------------------------------------------------
// Generic 3x3 conv + bias + PReLU, "same" padding, stride 1.
// Block: 256 threads = 32x8, spatial tile 32x16 (2 rows per thread),
// 16 output channels per block, CK=8 input channels per smem chunk.
// Each thread: 2 pixels x 16 couts = 32 fp32 accumulators.
// Weights broadcast across the warp (lanes differ only in pixel).
// ---------------------------------------------------------------------------
template <int CIN>
__global__ __launch_bounds__(256) void conv3_kernel(
    const float* __restrict__ in, const float* __restrict__ w,
    const float* __restrict__ b, const float* __restrict__ p,
    float* __restrict__ out) {
    constexpr int TW = 32, TH = 16, CK = 8, CB = 16;

    __shared__ __align__(16) float w_s[CK][9][CB];
    __shared__ float in_s[CK][TH + 2][TW + 2];

    const int tx = threadIdx.x & 31;  // 0..31
    const int ty = threadIdx.x >> 5;  // 0..7
    const int x0 = blockIdx.x * TW;
    const int y0 = blockIdx.y * TH;
    const int cb = blockIdx.z * CB;

    float acc0[CB], acc1[CB];
#pragma unroll
    for (int i = 0; i < CB; i++) { acc0[i] = 0.f; acc1[i] = 0.f; }

    for (int c0 = 0; c0 < CIN; c0 += CK) {
        __syncthreads();
        // Cooperative input tile load: (TH+2) x (TW+2) x CK, zero-padded edges.
        for (int i = threadIdx.x; i < CK * (TH + 2) * (TW + 2); i += 256) {
            int ck  = i / ((TH + 2) * (TW + 2));
            int rem = i - ck * ((TH + 2) * (TW + 2));
            int yy  = rem / (TW + 2);
            int xx  = rem - yy * (TW + 2);
            int gy = y0 + yy - 1, gx = x0 + xx - 1;
            float v = 0.f;
            if ((unsigned)gy < HH && (unsigned)gx < WW)
                v = in[(size_t)(c0 + ck) * HWSZ + gy * WW + gx];
            in_s[ck][yy][xx] = v;
        }
        // Cooperative weight load: CK x 9 x CB, co fastest (float4-friendly).
        for (int i = threadIdx.x; i < CK * 9 * CB; i += 256) {
            int ck  = i / (9 * CB);
            int rem = i - ck * 9 * CB;
            int tap = rem / CB;
            int co  = rem - tap * CB;
            w_s[ck][tap][co] = w[((size_t)(cb + co) * CIN + (c0 + ck)) * 9 + tap];
        }
        __syncthreads();

        for (int ck = 0; ck < CK; ck++) {
#pragma unroll
            for (int dy = 0; dy < 3; dy++) {
#pragma unroll
                for (int dx = 0; dx < 3; dx++) {
                    float v0 = in_s[ck][ty + dy][tx + dx];
                    float v1 = in_s[ck][ty + 8 + dy][tx + dx];
                    const float4* wp =
                        reinterpret_cast<const float4*>(&w_s[ck][dy * 3 + dx][0]);
#pragma unroll
                    for (int q = 0; q < CB / 4; q++) {
                        float4 wv = wp[q];
                        acc0[4*q+0] = fmaf(v0, wv.x, acc0[4*q+0]);
                        acc0[4*q+1] = fmaf(v0, wv.y, acc0[4*q+1]);
                        acc0[4*q+2] = fmaf(v0, wv.z, acc0[4*q+2]);
                        acc0[4*q+3] = fmaf(v0, wv.w, acc0[4*q+3]);
                        acc1[4*q+0] = fmaf(v1, wv.x, acc1[4*q+0]);
                        acc1[4*q+1] = fmaf(v1, wv.y, acc1[4*q+1]);
                        acc1[4*q+2] = fmaf(v1, wv.z, acc1[4*q+2]);
                        acc1[4*q+3] = fmaf(v1, wv.w, acc1[4*q+3]);
                    }
                }
            }
        }
    }

    float alpha = p[0];
#pragma unroll
    for (int co = 0; co < CB; co++) {
        float bb = b[cb + co];
        float v0 = acc0[co] + bb; v0 = v0 >= 0.f ? v0 : alpha * v0;
        float v1 = acc1[co] + bb; v1 = v1 >= 0.f ? v1 : alpha * v1;
        size_t base = (size_t)(cb + co) * HWSZ;
        out[base + (size_t)(y0 + ty) * WW + (x0 + tx)]     = v0;
        out[base + (size_t)(y0 + ty + 8) * WW + (x0 + tx)] = v1;
    }
}

// ---------------------------------------------------------------------------
// Layer 5: 64->1, k=3 + bias + PReLU. Tiny FLOPs; naive per-pixel kernel.
// ---------------------------------------------------------------------------
__global__ void conv3_last_kernel(const float* __restrict__ in,
                                  const float* __restrict__ w,
                                  const float* __restrict__ b,
                                  const float* __restrict__ p,
                                  float* __restrict__ out) {
    int x = blockIdx.x * 32 + (threadIdx.x & 31);
    int y = blockIdx.y * 8 + (threadIdx.x >> 5);
    float acc = 0.f;
    for (int ci = 0; ci < 64; ci++) {
#pragma unroll
        for (int dy = 0; dy < 3; dy++) {
            int gy = y + dy - 1;
            if ((unsigned)gy >= HH) continue;
#pragma unroll
            for (int dx = 0; dx < 3; dx++) {
                int gx = x + dx - 1;
                if ((unsigned)gx >= WW) continue;
                acc = fmaf(in[ci * HWSZ + gy * WW + gx], w[ci * 9 + dy * 3 + dx], acc);
            }
        }
    }
    float v = acc + b[0];
    v = v >= 0.f ? v : p[0] * v;
    out[y * WW + x] = v;
}

// ---------------------------------------------------------------------------
// Symmetrize: out = 0.5 * (t + t^T) over the spatial matrix.
// ---------------------------------------------------------------------------
__global__ void sym_kernel(const float* __restrict__ t, float* __restrict__ out) {
    int x = blockIdx.x * 32 + (threadIdx.x & 31);
    int y = blockIdx.y * 8 + (threadIdx.x >> 5);
    out[y * WW + x] = 0.5f * (t[y * WW + x] + t[x * WW + y]);
}

// ---------------------------------------------------------------------------
extern "C" void kernel_launch(void* const* d_in, const int* in_sizes, int n_in,
                              void* d_out, int out_size) {
    const float* A = (const float*)d_in[0];
    const float* wp[6]; const float* bp[6]; const float* pp[6];
    for (int i = 0; i < 6; i++) {
        wp[i] = (const float*)d_in[1 + 3 * i];
        bp[i] = (const float*)d_in[2 + 3 * i];
        pp[i] = (const float*)d_in[3 + 3 * i];
    }

    float *buf0, *buf1;
    cudaGetSymbolAddress((void**)&buf0, g_buf0);
    cudaGetSymbolAddress((void**)&buf1, g_buf1);

    // L0: 1 -> 64 (k=1)
    layer0_kernel<<<HWSZ / 256, 256>>>(A, wp[0], bp[0], pp[0]);
    // L1: 64 -> 256
    conv3_kernel<64><<<dim3(WW / 32, HH / 16, 256 / 16), 256>>>(buf0, wp[1], bp[1], pp[1], buf1);
    // L2: 256 -> 512
    conv3_kernel<256><<<dim3(WW / 32, HH / 16, 512 / 16), 256>>>(buf1, wp[2], bp[2], pp[2], buf0);
    // L3: 512 -> 256
    conv3_kernel<512><<<dim3(WW / 32, HH / 16, 256 / 16), 256>>>(buf0, wp[3], bp[3], pp[3], buf1);
    // L4: 256 -> 64
    conv3_kernel<256><<<dim3(WW / 32, HH / 16, 64 / 16), 256>>>(buf1, wp[4], bp[4], pp[4], buf0);
    // L5: 64 -> 1
    conv3_last_kernel<<<dim3(WW / 32, HH / 8), 256>>>(buf0, wp[5], bp[5], pp[5], buf1);
    // Symmetrize into d_out
    sym_kernel<<<dim3(WW / 32, HH / 8), 256>>>(buf1, (float*)d_out);
}